// round 7
// baseline (speedup 1.0000x reference)
#include <cuda_runtime.h>
#include <math.h>

// ARIMA sliding-window loss, algebraically collapsed to:
//   err[t] = y[t+33] - K1*FIR(g, win) + M1q*sum - K2q*sqrt(32*sq - sum^2 + 1024*eps)
//   loss   = (sum(y[:33]^2) + sum(err^2)) / S
// f32x2-packed FIR along the tap axis: chains with odd r use natural tap pairs
// (g0,g1)(g2,g3)... ; chains with even r use a pre-shifted copy (g1,g2)(g3,g4)...
// plus two scalar boundary FMAs. All packed operands are aligned smem u64 loads.

#define PW    32
#define T0    33
#define EPSF  1e-5f
#define TPB   128
#define RPT   8
#define TILE  (TPB * RPT)        // 1024 t per block
#define STAGE (TILE + 44)
#define MAXB  2048

typedef unsigned long long u64;
union F2U { u64 u; float2 f; };

__device__ double       g_part[MAXB];
__device__ unsigned int g_ctr = 0;   // atomicInc wraps to 0 each launch

__device__ __forceinline__ u64 ffma2(u64 a, u64 b, u64 c) {
    u64 d; asm("fma.rn.f32x2 %0, %1, %2, %3;" : "=l"(d) : "l"(a), "l"(b), "l"(c));
    return d;
}
__device__ __forceinline__ u64 fadd2(u64 a, u64 b) {
    u64 d; asm("add.rn.f32x2 %0, %1, %2;" : "=l"(d) : "l"(a), "l"(b));
    return d;
}
__device__ __forceinline__ float lo2(u64 v) { F2U t; t.u = v; return t.f.x; }
__device__ __forceinline__ float hi2(u64 v) { F2U t; t.u = v; return t.f.y; }
__device__ __forceinline__ float sqrt_apx(float x) {
    float r; asm("sqrt.approx.f32 %0, %1;" : "=f"(r) : "f"(x)); return r;
}
// FIR tap value g[j] from ar_weight
__device__ __forceinline__ float gval(const float* __restrict__ w, int j) {
    float gv = w[j] - ((j < PW - 1) ? w[j + 1] : 0.0f);
    if (j == PW - 2) gv -= 1.0f;
    if (j == PW - 1) gv += 1.0f;
    return gv;
}

__global__ void __launch_bounds__(TPB, 6) arima_fused(
    const float* __restrict__ y,
    const float* __restrict__ w,
    const float* __restrict__ ab,
    const float* __restrict__ rw_,
    const float* __restrict__ rb_,
    float* __restrict__ out,
    int T, int S)
{
    __shared__ __align__(16) float sy[STAGE];
    __shared__ __align__(16) float sg[PW];       // g[0..31]
    __shared__ __align__(16) u64   sgs[PW / 2];  // shifted pairs (g1,g2)(g3,g4)...(g29,g30)
    __shared__ float  sc[3];
    __shared__ double sred[TPB / 32];
    __shared__ int    isLast;

    const u64* syu = (const u64*)sy;
    const u64* sgu = (const u64*)sg;             // natural pairs (g0,g1)...
    const int tid = threadIdx.x;
    const int bid = blockIdx.x;
    const int tb  = bid * TILE;

    if (tid < PW) sg[tid] = gval(w, tid);
    if (tid < 15) {                              // sgs[k] = (g[2k+1], g[2k+2])
        F2U p; p.f.x = gval(w, 2 * tid + 1); p.f.y = gval(w, 2 * tid + 2);
        sgs[tid] = p.u;
    }
    if (tid == 0) {
        float rw = rw_[0], rb = rb_[0], b = ab[0], w0 = w[0];
        float denom = rw + EPSF * EPSF;
        float K1 = rw / denom;
        float K2 = (w0 * rb - rb + b) / denom;
        float M1 = fmaf(K1, w0, -1.0f);
        sc[0] = K1;
        sc[1] = K2 * (1.0f / 32.0f);
        sc[2] = M1 * (1.0f / 32.0f);
    }

    // Coalesced stage: sy[i] = y[tb+i] (aligned float4)
    {
        const float4* y4 = (const float4*)(y + tb);
        #pragma unroll
        for (int c = 0; c < 3; c++) {
            int i = tid + c * TPB;
            if (i < (STAGE >> 2)) {
                int gf = tb + 4 * i;
                float4 v;
                if (gf + 3 < S) v = y4[i];
                else {
                    v.x = (gf     < S) ? y[gf]     : 0.f;
                    v.y = (gf + 1 < S) ? y[gf + 1] : 0.f;
                    v.z = (gf + 2 < S) ? y[gf + 2] : 0.f;
                    v.w = (gf + 3 < S) ? y[gf + 3] : 0.f;
                }
                ((float4*)sy)[i] = v;
            }
        }
    }
    __syncthreads();

    const float K1 = sc[0], K2q = sc[1], M1q = sc[2];
    const float C0 = 1024.0f * EPSF;

    // Window pairs: wv[k] = (y[t0+2k], y[t0+2k+1]), k in [0,21). t0 = tb + 8*tid.
    const int t0 = tb + tid * RPT;
    u64 wv[21];
    #pragma unroll
    for (int k = 0; k < 21; k++) wv[k] = syu[4 * tid + k];

    #define XVm(m) (((m) & 1) ? hi2(wv[(m) >> 1]) : lo2(wv[(m) >> 1]))

    // Packed FIR. Chain r needs sum_j g[j]*xv[1+r+j].
    //  odd r:  full pairs  sum_k (g2k,g2k+1) . (wv[k + (1+r)/2])
    //  even r: shifted pairs sum_k (g2k+1,g2k+2) . (wv[k + 1 + r/2]) + g0*xv[1+r] + g31*xv[32+r]
    u64 acc[RPT];
    #pragma unroll
    for (int r = 0; r < RPT; r++) acc[r] = 0ull;
    #pragma unroll
    for (int k = 0; k < 16; k++) {
        u64 gpk = sgu[k];
        acc[1] = ffma2(gpk, wv[k + 1], acc[1]);
        acc[3] = ffma2(gpk, wv[k + 2], acc[3]);
        acc[5] = ffma2(gpk, wv[k + 3], acc[5]);
        acc[7] = ffma2(gpk, wv[k + 4], acc[7]);
        if (k < 15) {
            u64 gsk = sgs[k];
            acc[0] = ffma2(gsk, wv[k + 1], acc[0]);
            acc[2] = ffma2(gsk, wv[k + 2], acc[2]);
            acc[4] = ffma2(gsk, wv[k + 3], acc[4]);
            acc[6] = ffma2(gsk, wv[k + 4], acc[6]);
        }
    }
    const float g0 = sg[0], g31 = sg[PW - 1];
    float f[RPT];
    #pragma unroll
    for (int r = 0; r < RPT; r++) {
        f[r] = lo2(acc[r]) + hi2(acc[r]);
        if ((r & 1) == 0) {
            f[r] = fmaf(g0,  XVm(1 + r),  f[r]);
            f[r] = fmaf(g31, XVm(32 + r), f[r]);
        }
    }

    // Packed sum/sumsq over xv[0..31], then adjust to xv[1..32]
    u64 s2 = 0ull, q2 = 0ull;
    #pragma unroll
    for (int k = 0; k < 16; k++) {
        s2 = fadd2(s2, wv[k]);
        q2 = ffma2(wv[k], wv[k], q2);
    }
    float x0 = XVm(0), x32 = XVm(32);
    float sum = lo2(s2) + hi2(s2) - x0 + x32;
    float sq  = lo2(q2) + hi2(q2);
    sq = fmaf(-x0, x0, sq);
    sq = fmaf(x32, x32, sq);

    float esum_f = 0.0f;
    if (t0 + RPT <= T) {                 // interior fast path
        #pragma unroll
        for (int r = 0; r < RPT; r++) {
            if (r > 0) {
                float xn = XVm(32 + r), xo = XVm(r);
                sum += xn - xo;
                sq   = fmaf(xn, xn, sq);
                sq   = fmaf(-xo, xo, sq);
            }
            float u   = fmaf(-sum, sum, 32.0f * sq);
            float sd  = sqrt_apx(u + C0);
            float err = fmaf(-K2q, sd, fmaf(M1q, sum, fmaf(-K1, f[r], XVm(33 + r))));
            esum_f = fmaf(err, err, esum_f);
        }
    } else {
        #pragma unroll
        for (int r = 0; r < RPT; r++) {
            if (r > 0) {
                float xn = XVm(32 + r), xo = XVm(r);
                sum += xn - xo;
                sq   = fmaf(xn, xn, sq);
                sq   = fmaf(-xo, xo, sq);
            }
            if (t0 + r < T) {
                float u   = fmaf(-sum, sum, 32.0f * sq);
                float sd  = sqrt_apx(u + C0);
                float err = fmaf(-K2q, sd, fmaf(M1q, sum, fmaf(-K1, f[r], XVm(33 + r))));
                esum_f = fmaf(err, err, esum_f);
            }
        }
    }

    // Block reduction (double from warp level up)
    double esum = (double)esum_f;
    #pragma unroll
    for (int o = 16; o > 0; o >>= 1)
        esum += __shfl_down_sync(0xffffffffu, esum, o);
    if ((tid & 31) == 0) sred[tid >> 5] = esum;
    __syncthreads();
    if (tid == 0) {
        double bs = 0.0;
        #pragma unroll
        for (int i = 0; i < TPB / 32; i++) bs += sred[i];
        g_part[bid] = bs;
        __threadfence();
        unsigned pos = atomicInc(&g_ctr, gridDim.x - 1);
        isLast = (pos == gridDim.x - 1);
    }
    __syncthreads();

    // Last block: deterministic final reduction + head term
    if (isLast) {
        __threadfence();
        double s = 0.0;
        for (int i = tid; i < (int)gridDim.x; i += TPB) s += g_part[i];
        for (int i = tid; i < T0; i += TPB) { double v = (double)y[i]; s += v * v; }
        #pragma unroll
        for (int o = 16; o > 0; o >>= 1)
            s += __shfl_down_sync(0xffffffffu, s, o);
        if ((tid & 31) == 0) sred[tid >> 5] = s;
        __syncthreads();
        if (tid == 0) {
            double tot = 0.0;
            #pragma unroll
            for (int i = 0; i < TPB / 32; i++) tot += sred[i];
            out[0] = (float)(tot / (double)S);
        }
    }
}

extern "C" void kernel_launch(void* const* d_in, const int* in_sizes, int n_in,
                              void* d_out, int out_size)
{
    const float* y  = (const float*)d_in[0];
    const float* w  = (const float*)d_in[1];
    const float* ab = (const float*)d_in[2];
    const float* rw = (const float*)d_in[3];
    const float* rb = (const float*)d_in[4];
    int S = in_sizes[0];
    int T = S - T0;
    int nblocks = (T + TILE - 1) / TILE;   // S=1M -> 1024 blocks
    if (nblocks > MAXB) nblocks = MAXB;
    arima_fused<<<nblocks, TPB>>>(y, w, ab, rw, rb, (float*)d_out, T, S);
}

// round 8
// speedup vs baseline: 1.1629x; 1.1629x over previous
#include <cuda_runtime.h>
#include <math.h>

// ARIMA sliding-window loss, algebraically collapsed to:
//   err[t] = y[t+33] - K1*FIR(g, win) + M1q*sum - K2q*sqrt(32*sq - sum^2 + 1024*eps)
//   loss   = (sum(y[:33]^2) + sum(err^2)) / S
// R6 structure + 128B-XOR-swizzled smem staging so the 32B-lane-stride window
// reads (LDS.128) are bank-conflict-free (8 -> 4 wavefronts per access).

#define PW    32
#define T0    33
#define EPSF  1e-5f
#define TPB   128
#define RPT   8
#define TILE  (TPB * RPT)        // 1024 t per block
#define STAGE 1088               // padded to 128B multiple; need 1068 floats
#define MAXB  2048

// XOR swizzle on byte offsets: permutes 16B chunks within each 128B line group
#define SWZ(b) ((b) ^ (((b) >> 3) & 0x70))

__device__ double       g_part[MAXB];
__device__ unsigned int g_ctr = 0;   // atomicInc wraps to 0 each launch

__device__ __forceinline__ float sqrt_apx(float x) {
    float r; asm("sqrt.approx.f32 %0, %1;" : "=f"(r) : "f"(x)); return r;
}

__global__ void __launch_bounds__(TPB, 7) arima_fused(
    const float* __restrict__ y,
    const float* __restrict__ w,
    const float* __restrict__ ab,
    const float* __restrict__ rw_,
    const float* __restrict__ rb_,
    float* __restrict__ out,
    int T, int S)
{
    __shared__ __align__(128) float sy[STAGE];   // swizzled storage of y[tb .. tb+1068)
    __shared__ __align__(16)  float sg[PW];
    __shared__ float  sc[3];
    __shared__ double sred[TPB / 32];
    __shared__ int    isLast;

    const float4* sg4 = (const float4*)sg;
    const int tid = threadIdx.x;
    const int bid = blockIdx.x;
    const int tb  = bid * TILE;

    // FIR taps from ar_weight + differencing structure
    if (tid < PW) {
        float wj  = w[tid];
        float wj1 = (tid < PW - 1) ? w[tid + 1] : 0.0f;
        float gv  = wj - wj1;
        if (tid == PW - 2) gv -= 1.0f;   // g[30] = w30 - w31 - 1
        if (tid == PW - 1) gv += 1.0f;   // g[31] = w31 + 1
        sg[tid] = gv;
    }
    if (tid == 0) {
        float rw = rw_[0], rb = rb_[0], b = ab[0], w0 = w[0];
        float denom = rw + EPSF * EPSF;
        float K1 = rw / denom;
        float K2 = (w0 * rb - rb + b) / denom;
        float M1 = fmaf(K1, w0, -1.0f);
        sc[0] = K1;
        sc[1] = K2 * (1.0f / 32.0f);      // K2q
        sc[2] = M1 * (1.0f / 32.0f);      // M1q
    }

    // Coalesced stage, swizzled store: chunk i holds y[tb+4i .. +3]
    {
        const float4* y4 = (const float4*)(y + tb);
        #pragma unroll
        for (int c = 0; c < 3; c++) {
            int i = tid + c * TPB;                 // float4 chunk index
            if (i < 267) {                         // 1068/4
                int gf = tb + 4 * i;
                float4 v;
                if (gf + 3 < S) v = y4[i];
                else {
                    v.x = (gf     < S) ? y[gf]     : 0.f;
                    v.y = (gf + 1 < S) ? y[gf + 1] : 0.f;
                    v.z = (gf + 2 < S) ? y[gf + 2] : 0.f;
                    v.w = (gf + 3 < S) ? y[gf + 3] : 0.f;
                }
                *(float4*)((char*)sy + SWZ(16 * i)) = v;
            }
        }
    }
    __syncthreads();

    const float K1 = sc[0], K2q = sc[1], M1q = sc[2];
    const float C0 = 1024.0f * EPSF;

    // Window: xv[m] = y[t0+m], m in [0,44), t0 = tb + 8*tid.
    // 11 swizzled LDS.128 at chunk = 2*tid + c  -> conflict-free under SWZ.
    const int t0 = tb + tid * RPT;
    float xv[44];
    #pragma unroll
    for (int c = 0; c < 11; c++) {
        int k = 2 * tid + c;
        float4 v = *(const float4*)((const char*)sy + SWZ(16 * k));
        xv[4*c + 0] = v.x; xv[4*c + 1] = v.y;
        xv[4*c + 2] = v.z; xv[4*c + 3] = v.w;
    }

    // 8 FIR chains over xv[1+r .. 32+r] + initial sum/sumsq over xv[1..32]
    float f[RPT];
    #pragma unroll
    for (int r = 0; r < RPT; r++) f[r] = 0.0f;
    float sum = 0.f, sq = 0.f;
    #pragma unroll
    for (int c = 0; c < 8; c++) {
        float4 gc = sg4[c];
        const float ge[4] = {gc.x, gc.y, gc.z, gc.w};
        #pragma unroll
        for (int e = 0; e < 4; e++) {
            const int j = 4 * c + e;
            float xj = xv[1 + j];
            sum += xj;
            sq   = fmaf(xj, xj, sq);
            #pragma unroll
            for (int r = 0; r < RPT; r++)
                f[r] = fmaf(ge[e], xv[1 + j + r], f[r]);
        }
    }

    float esum_f = 0.0f;
    if (t0 + RPT <= T) {                 // interior: no per-r bound checks
        #pragma unroll
        for (int r = 0; r < RPT; r++) {
            if (r > 0) {
                float xn = xv[32 + r], xo = xv[r];
                sum += xn - xo;
                sq   = fmaf(xn, xn, sq);
                sq   = fmaf(-xo, xo, sq);
            }
            float u   = fmaf(-sum, sum, 32.0f * sq);
            float sd  = sqrt_apx(u + C0);
            float err = fmaf(-K2q, sd, fmaf(M1q, sum, fmaf(-K1, f[r], xv[33 + r])));
            esum_f = fmaf(err, err, esum_f);
        }
    } else {
        #pragma unroll
        for (int r = 0; r < RPT; r++) {
            if (r > 0) {
                float xn = xv[32 + r], xo = xv[r];
                sum += xn - xo;
                sq   = fmaf(xn, xn, sq);
                sq   = fmaf(-xo, xo, sq);
            }
            if (t0 + r < T) {
                float u   = fmaf(-sum, sum, 32.0f * sq);
                float sd  = sqrt_apx(u + C0);
                float err = fmaf(-K2q, sd, fmaf(M1q, sum, fmaf(-K1, f[r], xv[33 + r])));
                esum_f = fmaf(err, err, esum_f);
            }
        }
    }

    // Block reduction (double from warp level up)
    double esum = (double)esum_f;
    #pragma unroll
    for (int o = 16; o > 0; o >>= 1)
        esum += __shfl_down_sync(0xffffffffu, esum, o);
    if ((tid & 31) == 0) sred[tid >> 5] = esum;
    __syncthreads();
    if (tid == 0) {
        double bs = 0.0;
        #pragma unroll
        for (int i = 0; i < TPB / 32; i++) bs += sred[i];
        g_part[bid] = bs;
        __threadfence();
        unsigned pos = atomicInc(&g_ctr, gridDim.x - 1);
        isLast = (pos == gridDim.x - 1);
    }
    __syncthreads();

    // Last block: deterministic final reduction + head term
    if (isLast) {
        __threadfence();
        double s = 0.0;
        for (int i = tid; i < (int)gridDim.x; i += TPB) s += g_part[i];
        for (int i = tid; i < T0; i += TPB) { double v = (double)y[i]; s += v * v; }
        #pragma unroll
        for (int o = 16; o > 0; o >>= 1)
            s += __shfl_down_sync(0xffffffffu, s, o);
        if ((tid & 31) == 0) sred[tid >> 5] = s;
        __syncthreads();
        if (tid == 0) {
            double tot = 0.0;
            #pragma unroll
            for (int i = 0; i < TPB / 32; i++) tot += sred[i];
            out[0] = (float)(tot / (double)S);
        }
    }
}

extern "C" void kernel_launch(void* const* d_in, const int* in_sizes, int n_in,
                              void* d_out, int out_size)
{
    const float* y  = (const float*)d_in[0];
    const float* w  = (const float*)d_in[1];
    const float* ab = (const float*)d_in[2];
    const float* rw = (const float*)d_in[3];
    const float* rb = (const float*)d_in[4];
    int S = in_sizes[0];
    int T = S - T0;
    int nblocks = (T + TILE - 1) / TILE;   // S=1M -> 1024 blocks, fully resident
    if (nblocks > MAXB) nblocks = MAXB;
    arima_fused<<<nblocks, TPB>>>(y, w, ab, rw, rb, (float*)d_out, T, S);
}